// round 1
// baseline (speedup 1.0000x reference)
#include <cuda_runtime.h>
#include <math.h>

#define NN 10000
#define NE 320000
#define SD 128
#define VD 64
#define V3 192
#define NWW 448
#define TILE 4
#define THREADS 256

// ---------------- scratch (static device globals; no runtime allocation) ----
__device__ float g_ms[NN*SD];
__device__ float g_ds[NN*SD];
__device__ float g_mv[NN*V3];
__device__ float g_dv[NN*V3];
__device__ float g_vals[NE*SD];     // per-edge val_s
__device__ float g_valv[NE*V3];     // per-edge val_v
__device__ float g_logit[NE*4];
__device__ float g_zz[NE*4];
__device__ unsigned int g_menc[NN*4];
__device__ float g_den[NN*4];
__device__ float g_outs[NN*SD];
__device__ float g_outv[NN*V3];

// monotone float<->uint order encoding for atomicMax on floats
__device__ __forceinline__ unsigned f2ord(float f){
    unsigned u = __float_as_uint(f);
    return (u & 0x80000000u) ? ~u : (u | 0x80000000u);
}
__device__ __forceinline__ float ord2f(unsigned u){
    return (u & 0x80000000u) ? __uint_as_float(u ^ 0x80000000u)
                             : __uint_as_float(~u);
}

// ---------------- tiled GEMM helpers (per edge-tile, weights from gmem) -----
// X: smem [TILE][NIN] contiguous. Y: smem [TILE][NOUT]. W row-major [NIN][NOUT].
// ACT: 0 = none, 1 = silu
template<int NIN, int NOUT, int ACT>
__device__ __forceinline__ void gemm_tile(const float* __restrict__ W,
                                          const float* __restrict__ bias,
                                          const float* __restrict__ X,
                                          float* __restrict__ Y)
{
    constexpr int G0  = (NOUT >= THREADS) ? 1 : (THREADS / NOUT);
    constexpr int G   = (G0 > TILE) ? TILE : G0;
    constexpr int EPT = TILE / G;
    const int tid = threadIdx.x;
    int g, j0;
    if (NOUT >= THREADS) { g = 0; j0 = tid; }
    else                 { g = tid / NOUT; j0 = tid - g * NOUT; }
    if (g < G) {
        const float* xb = X + g * EPT * NIN;
        for (int j = j0; j < NOUT; j += THREADS) {
            float acc[EPT];
            #pragma unroll
            for (int u = 0; u < EPT; u++) acc[u] = 0.f;
            #pragma unroll 4
            for (int i = 0; i < NIN; i++) {
                float wv = W[i * NOUT + j];
                #pragma unroll
                for (int u = 0; u < EPT; u++)
                    acc[u] = fmaf(wv, xb[u * NIN + i], acc[u]);
            }
            float bv = bias ? bias[j] : 0.f;
            #pragma unroll
            for (int u = 0; u < EPT; u++) {
                float r = acc[u] + bv;
                if (ACT == 1) r = r / (1.f + expf(-r));
                Y[(g * EPT + u) * NOUT + j] = r;
            }
        }
    }
}

// Vector GEMM: out[e][d][i] = sum_c X[e][c][i] * W[c][d],  W [NIN][64]
// X smem [TILE][NIN*3] (c*3+i), Y smem [TILE][192] (d*3+i)
template<int NIN>
__device__ __forceinline__ void gemm_vec_tile(const float* __restrict__ W,
                                              const float* __restrict__ X,
                                              float* __restrict__ Y)
{
    const int tid = threadIdx.x;
    if (tid < 192) {
        const int i = tid >> 6;
        const int d = tid & 63;
        float acc[TILE];
        #pragma unroll
        for (int u = 0; u < TILE; u++) acc[u] = 0.f;
        #pragma unroll 4
        for (int c = 0; c < NIN; c++) {
            float wv = W[c * 64 + d];
            #pragma unroll
            for (int u = 0; u < TILE; u++)
                acc[u] = fmaf(wv, X[u * (NIN*3) + c*3 + i], acc[u]);
        }
        #pragma unroll
        for (int u = 0; u < TILE; u++)
            Y[u * 192 + d*3 + i] = acc[u];
    }
}

// ---------------- K0: init accumulators ------------------------------------
__global__ void init_kernel() {
    int i = blockIdx.x * blockDim.x + threadIdx.x;
    int stride = gridDim.x * blockDim.x;
    if (i < NN*4) { g_menc[i] = 0u; g_den[i] = 0.f; }
    for (int k = i; k < NN*SD; k += stride) g_outs[k] = 0.f;
    for (int k = i; k < NN*V3; k += stride) g_outv[k] = 0.f;
}

// ---------------- K1: node pre-linears --------------------------------------
__global__ __launch_bounds__(128) void node_pre(
    const float* __restrict__ ni,
    const float* __restrict__ Wss, const float* __restrict__ bss,
    const float* __restrict__ Wsv,
    const float* __restrict__ Wds, const float* __restrict__ Wdv)
{
    int n = blockIdx.x, tid = threadIdx.x;
    __shared__ float s[128], v[192];
    s[tid] = ni[n*320 + tid];
    for (int k = tid; k < 192; k += 128) v[k] = ni[n*320 + 128 + k];
    __syncthreads();
    float a1 = bss[tid], a2 = 0.f;
    #pragma unroll 4
    for (int i = 0; i < 128; i++) {
        float si = s[i];
        a1 = fmaf(si, Wss[i*128 + tid], a1);
        a2 = fmaf(si, Wds[i*128 + tid], a2);
    }
    g_ms[n*128 + tid] = a1;
    g_ds[n*128 + tid] = a2;
    for (int o = tid; o < 192; o += 128) {
        int i = o >> 6, d = o & 63;
        float m1 = 0.f, m2 = 0.f;
        #pragma unroll 4
        for (int c = 0; c < 64; c++) {
            float x = v[c*3 + i];
            m1 = fmaf(x, Wsv[c*64 + d], m1);
            m2 = fmaf(x, Wdv[c*64 + d], m2);
        }
        g_mv[n*192 + d*3 + i] = m1;
        g_dv[n*192 + d*3 + i] = m2;
    }
}

// ---------------- K2: fused per-edge megakernel -----------------------------
__global__ __launch_bounds__(THREADS) void edge_kernel(
    const int*   __restrict__ esrc, const int* __restrict__ edst,
    const float* __restrict__ eattr, const float* __restrict__ eemb,
    const float* __restrict__ nattr,
    const float* __restrict__ rW0, const float* __restrict__ rb0,
    const float* __restrict__ rW1, const float* __restrict__ rb1,
    const float* __restrict__ rW2, const float* __restrict__ rb2,
    const float* __restrict__ attWs, const float* __restrict__ attbs,
    const float* __restrict__ l1Ws, const float* __restrict__ l1bs,
    const float* __restrict__ l1Wv, const float* __restrict__ tp2w,
    const float* __restrict__ l2Ws, const float* __restrict__ l2bs,
    const float* __restrict__ l2Wv, const float* __restrict__ attdot)
{
    __shared__ float sm[8784];
    __shared__ int ssrc[TILE], sdst[TILE];
    const int tid = threadIdx.x;
    const int e0  = blockIdx.x * TILE;

    // phase-overlaid buffers
    float* es  = sm;            // [4][128] (early)
    float* ev  = sm + 512;      // [4][192] (early)
    float* wb  = sm + 1280;     // [4][448] (early)
    float* sc  = sm;            // [4][128] (late, over es)
    float* gs  = sm + 512;      // [4][192] (late, over ev)
    float* gv  = sm + 1280;     // [4][192] (late, over wb lo)
    float* vls = sm + 2048;     // [4][128] (late, over wb mid)
    float* vlv = sm + 2560;     // [4][192] (late, over wb hi)
    float* wf  = sm + 3328;     // [4][160]
    float* h0  = sm + 3968;     // [4][64]
    float* h1  = sm + 4224;     // [4][64]
    float* stp = sm + 4480;     // [4][192]  (reused by s2)
    float* vtp = sm + 5248;     // [4][768]  (reused by v2)
    float* yv  = sm + 8320;     // [4][4]
    float* w2s = sm + 8336;     // [448]

    if (tid < TILE)   { ssrc[tid] = esrc[e0 + tid]; sdst[tid] = edst[e0 + tid]; }
    if (tid < TILE*4) yv[tid] = eattr[e0*4 + tid];
    for (int t = tid; t < NWW; t += THREADS) w2s[t] = tp2w[t];
    __syncthreads();

    // A: gather es, ev; assemble wf
    for (int t = tid; t < TILE*SD; t += THREADS) {
        int e = t >> 7, j = t & 127;
        es[t] = g_ms[ssrc[e]*SD + j] + g_ds[sdst[e]*SD + j];
    }
    for (int t = tid; t < TILE*V3; t += THREADS) {
        int e = t / V3, k = t - e*V3;
        ev[t] = g_mv[ssrc[e]*V3 + k] + g_dv[sdst[e]*V3 + k];
    }
    for (int t = tid; t < TILE*160; t += THREADS) {
        int e = t / 160, k = t - e*160;
        float val;
        if (k < 32)       val = eemb[(e0+e)*32 + k];
        else if (k < 96)  val = nattr[ssrc[e]*64 + (k-32)];
        else              val = nattr[sdst[e]*64 + (k-96)];
        wf[t] = val;
    }
    __syncthreads();

    // B: radial MLP 160 -> 64 -> 64 -> 448
    gemm_tile<160, 64, 1>(rW0, rb0, wf, h0);
    __syncthreads();
    gemm_tile< 64, 64, 1>(rW1, rb1, h0, h1);
    __syncthreads();
    gemm_tile< 64,448, 0>(rW2, rb2, h1, wb);
    __syncthreads();

    // C: DTP1 (es, ev, wb, y) -> stp [4][192], vtp [4][768]
    for (int t = tid; t < TILE*192; t += THREADS) {
        int e = t / 192, c = t - e*192;
        float y0 = yv[e*4];
        if (c < 128) {
            stp[t] = wb[e*448 + c] * es[e*128 + c] * y0;
        } else {
            int cc = c - 128;
            float vx = ev[e*192 + cc*3], vy = ev[e*192 + cc*3+1], vz = ev[e*192 + cc*3+2];
            stp[t] = wb[e*448 + 320 + cc] *
                     (vx*yv[e*4+1] + vy*yv[e*4+2] + vz*yv[e*4+3]);
        }
    }
    for (int t = tid; t < TILE*256; t += THREADS) {
        int e = t >> 8, c = t & 255;
        float y0 = yv[e*4], y1x = yv[e*4+1], y1y = yv[e*4+2], y1z = yv[e*4+3];
        float* o = vtp + e*768 + c*3;
        if (c < 128) {
            float a = wb[e*448 + 128 + c] * es[e*128 + c];
            o[0] = a*y1x; o[1] = a*y1y; o[2] = a*y1z;
        } else if (c < 192) {
            int cc = c - 128;
            float a = wb[e*448 + 256 + cc] * y0;
            o[0] = a*ev[e*192 + cc*3];
            o[1] = a*ev[e*192 + cc*3+1];
            o[2] = a*ev[e*192 + cc*3+2];
        } else {
            int cc = c - 192;
            float wc = wb[e*448 + 384 + cc];
            float vx = ev[e*192 + cc*3], vy = ev[e*192 + cc*3+1], vz = ev[e*192 + cc*3+2];
            o[0] = wc*(vy*y1z - vz*y1y);
            o[1] = wc*(vz*y1x - vx*y1z);
            o[2] = wc*(vx*y1y - vy*y1x);
        }
    }
    __syncthreads();

    // D: sc / gs / gv (all read stp/vtp, write disjoint dead regions)
    gemm_tile<192,128,0>(attWs, attbs, stp, sc);
    gemm_tile<192,192,0>(l1Ws,  l1bs,  stp, gs);
    gemm_vec_tile<256>(l1Wv, vtp, gv);
    __syncthreads();

    // E: gates in place (fs over gs[0:128], fv over gv)
    for (int t = tid; t < TILE*128; t += THREADS) {
        int e = t >> 7, c = t & 127;
        float x = gs[e*192 + c];
        gs[e*192 + c] = x / (1.f + expf(-x));
    }
    for (int t = tid; t < TILE*64; t += THREADS) {
        int e = t >> 6, c = t & 63;
        float sg = 1.f / (1.f + expf(-gs[e*192 + 128 + c]));
        gv[e*192 + c*3]   *= sg;
        gv[e*192 + c*3+1] *= sg;
        gv[e*192 + c*3+2] *= sg;
    }
    __syncthreads();

    // F: DTP2 (fs=gs, fv=gv, tp2w, y) -> s2 (stp), v2 (vtp)
    for (int t = tid; t < TILE*192; t += THREADS) {
        int e = t / 192, c = t - e*192;
        float y0 = yv[e*4];
        if (c < 128) {
            stp[t] = w2s[c] * gs[e*192 + c] * y0;
        } else {
            int cc = c - 128;
            float vx = gv[e*192 + cc*3], vy = gv[e*192 + cc*3+1], vz = gv[e*192 + cc*3+2];
            stp[t] = w2s[320 + cc] *
                     (vx*yv[e*4+1] + vy*yv[e*4+2] + vz*yv[e*4+3]);
        }
    }
    for (int t = tid; t < TILE*256; t += THREADS) {
        int e = t >> 8, c = t & 255;
        float y0 = yv[e*4], y1x = yv[e*4+1], y1y = yv[e*4+2], y1z = yv[e*4+3];
        float* o = vtp + e*768 + c*3;
        if (c < 128) {
            float a = w2s[128 + c] * gs[e*192 + c];
            o[0] = a*y1x; o[1] = a*y1y; o[2] = a*y1z;
        } else if (c < 192) {
            int cc = c - 128;
            float a = w2s[256 + cc] * y0;
            o[0] = a*gv[e*192 + cc*3];
            o[1] = a*gv[e*192 + cc*3+1];
            o[2] = a*gv[e*192 + cc*3+2];
        } else {
            int cc = c - 192;
            float wc = w2s[384 + cc];
            float vx = gv[e*192 + cc*3], vy = gv[e*192 + cc*3+1], vz = gv[e*192 + cc*3+2];
            o[0] = wc*(vy*y1z - vz*y1y);
            o[1] = wc*(vz*y1x - vx*y1z);
            o[2] = wc*(vx*y1y - vy*y1x);
        }
    }
    __syncthreads();

    // G: val_s / val_v
    gemm_tile<192,128,0>(l2Ws, l2bs, stp, vls);
    gemm_vec_tile<256>(l2Wv, vtp, vlv);
    __syncthreads();

    // H: logits + stores
    if (tid < TILE*4) {
        int e = tid >> 2, h = tid & 3;
        float acc = 0.f;
        #pragma unroll 4
        for (int k = 0; k < 32; k++) {
            float x = sc[e*128 + h*32 + k];
            float sg = 1.f / (1.f + expf(-x));
            float sl = 0.6f*x + 0.4f*x*(2.f*sg - 1.f);
            acc = fmaf(sl, attdot[h*32 + k], acc);
        }
        g_logit[(e0+e)*4 + h] = acc;
        atomicMax(&g_menc[sdst[e]*4 + h], f2ord(acc));
    }
    for (int t = tid; t < TILE*SD; t += THREADS)
        g_vals[e0*SD + t] = vls[t];
    for (int t = tid; t < TILE*V3; t += THREADS)
        g_valv[e0*V3 + t] = vlv[t];
}

// ---------------- K3: z = exp(logit - m), accumulate den --------------------
__global__ void softmax_z(const int* __restrict__ edst) {
    int i = blockIdx.x * blockDim.x + threadIdx.x;
    if (i >= NE*4) return;
    int e = i >> 2, h = i & 3;
    int d = edst[e];
    float m = ord2f(g_menc[d*4 + h]);
    float z = expf(g_logit[i] - m);
    g_zz[i] = z;
    atomicAdd(&g_den[d*4 + h], z);
}

// ---------------- K4: alpha-weighted scatter --------------------------------
__global__ __launch_bounds__(192) void scatter_kernel(const int* __restrict__ edst) {
    int e = blockIdx.x;
    int tid = threadIdx.x;
    __shared__ float a[4];
    int d = edst[e];
    if (tid < 4) a[tid] = g_zz[e*4 + tid] / (g_den[d*4 + tid] + 1e-12f);
    __syncthreads();
    if (tid < 128)
        atomicAdd(&g_outs[d*128 + tid], g_vals[e*128 + tid] * a[tid >> 5]);
    atomicAdd(&g_outv[d*192 + tid], g_valv[e*192 + tid] * a[(tid/3) >> 4]);
}

// ---------------- K5: final node linears -> d_out ---------------------------
__global__ __launch_bounds__(128) void node_post(
    const float* __restrict__ oWs, const float* __restrict__ obs,
    const float* __restrict__ oWv, float* __restrict__ out)
{
    int n = blockIdx.x, tid = threadIdx.x;
    __shared__ float os[128], ov[192];
    os[tid] = g_outs[n*128 + tid];
    for (int k = tid; k < 192; k += 128) ov[k] = g_outv[n*192 + k];
    __syncthreads();
    float acc = obs[tid];
    #pragma unroll 4
    for (int i = 0; i < 128; i++)
        acc = fmaf(os[i], oWs[i*128 + tid], acc);
    out[n*320 + tid] = acc;
    for (int o = tid; o < 192; o += 128) {
        int i = o >> 6, d = o & 63;
        float a2 = 0.f;
        #pragma unroll 4
        for (int c = 0; c < 64; c++)
            a2 = fmaf(ov[c*3 + i], oWv[c*64 + d], a2);
        out[n*320 + 128 + d*3 + i] = a2;
    }
}

// ---------------- host launcher ---------------------------------------------
extern "C" void kernel_launch(void* const* d_in, const int* in_sizes, int n_in,
                              void* d_out, int out_size)
{
    const float* node_input = (const float*)d_in[0];
    const float* node_attr  = (const float*)d_in[1];
    const int *esrc, *edst;
    const float *eattr, *eemb;
    if (in_sizes[2] == NE) {           // reference-signature order
        esrc  = (const int*)d_in[2];
        edst  = (const int*)d_in[3];
        eattr = (const float*)d_in[4];
        eemb  = (const float*)d_in[5];
    } else {                            // setup_inputs dict order
        eattr = (const float*)d_in[2];
        eemb  = (const float*)d_in[3];
        esrc  = (const int*)d_in[4];
        edst  = (const int*)d_in[5];
    }
    const float* Wss   = (const float*)d_in[6];
    const float* bss   = (const float*)d_in[7];
    const float* Wsv   = (const float*)d_in[8];
    const float* Wds   = (const float*)d_in[9];
    const float* Wdv   = (const float*)d_in[10];
    const float* rW0   = (const float*)d_in[11];
    const float* rb0   = (const float*)d_in[12];
    const float* rW1   = (const float*)d_in[13];
    const float* rb1   = (const float*)d_in[14];
    const float* rW2   = (const float*)d_in[15];
    const float* rb2   = (const float*)d_in[16];
    const float* l1Ws  = (const float*)d_in[17];
    const float* l1bs  = (const float*)d_in[18];
    const float* l1Wv  = (const float*)d_in[19];
    const float* attWs = (const float*)d_in[20];
    const float* attbs = (const float*)d_in[21];
    const float* tp2w  = (const float*)d_in[22];
    const float* l2Ws  = (const float*)d_in[23];
    const float* l2bs  = (const float*)d_in[24];
    const float* l2Wv  = (const float*)d_in[25];
    const float* attdot= (const float*)d_in[26];
    const float* oWs   = (const float*)d_in[27];
    const float* obs   = (const float*)d_in[28];
    const float* oWv   = (const float*)d_in[29];

    init_kernel<<<(NN*V3 + 255)/256, 256>>>();
    node_pre<<<NN, 128>>>(node_input, Wss, bss, Wsv, Wds, Wdv);
    edge_kernel<<<NE/TILE, THREADS>>>(esrc, edst, eattr, eemb, node_attr,
                                      rW0, rb0, rW1, rb1, rW2, rb2,
                                      attWs, attbs, l1Ws, l1bs, l1Wv,
                                      tp2w, l2Ws, l2bs, l2Wv, attdot);
    softmax_z<<<(NE*4 + 255)/256, 256>>>(edst);
    scatter_kernel<<<NE, 192>>>(edst);
    node_post<<<NN, 128>>>(oWs, obs, oWv, (float*)d_out);
}

// round 2
// speedup vs baseline: 1.4778x; 1.4778x over previous
#include <cuda_runtime.h>
#include <math.h>

#define NN 10000
#define NE 320000
#define SD 128
#define VD 64
#define V3 192
#define NWW 448
#define EB 8
#define THREADS 256

// ---------------- scratch (static device globals; no runtime allocation) ----
__device__ __align__(16) float g_ms[NN*SD];
__device__ __align__(16) float g_ds[NN*SD];
__device__ __align__(16) float g_mv[NN*V3];   // [n][c*3+i]
__device__ __align__(16) float g_dv[NN*V3];
__device__ __align__(16) float g_vals[NE*SD]; // [e][128]
__device__ __align__(16) float g_valv[NE*V3]; // [e][i*64+d]
__device__ float g_logit[NE*4];
__device__ float g_zz[NE*4];
__device__ unsigned int g_menc[NN*4];
__device__ float g_den[NN*4];
__device__ __align__(16) float g_outs[NN*SD];
__device__ __align__(16) float g_outv[NN*V3]; // [n][i*64+d]

// monotone float<->uint order encoding for atomicMax on floats
__device__ __forceinline__ unsigned f2ord(float f){
    unsigned u = __float_as_uint(f);
    return (u & 0x80000000u) ? ~u : (u | 0x80000000u);
}
__device__ __forceinline__ float ord2f(unsigned u){
    return (u & 0x80000000u) ? __uint_as_float(u ^ 0x80000000u)
                             : __uint_as_float(~u);
}

// ---------------- register-tiled batched GEMM -------------------------------
// X smem [ROWS][NIN], W gmem [NIN][NOUT], Y smem [ROWS][NOUT].
// Each active thread computes a TM x TN register tile. ACT: 0 none, 1 silu.
template<int NIN, int NOUT, int ROWS, int TM, int TN, int ACT>
__device__ __forceinline__ void gemm_rt(const float* __restrict__ W,
                                        const float* __restrict__ bias,
                                        const float* __restrict__ X,
                                        float* __restrict__ Y)
{
    constexpr int R = ROWS / TM;
    constexpr int C = NOUT / TN;
    static_assert(R * TM == ROWS && C * TN == NOUT, "tile mismatch");
    static_assert(R * C <= THREADS, "too many threads");
    const int t = threadIdx.x;
    if (t < R * C) {
        const int cj = (t % C) * TN;
        const int r0 = (t / C) * TM;
        const float* xb = X + r0 * NIN;
        float* yb = Y + r0 * NOUT + cj;
        float acc[TM][TN];
        #pragma unroll
        for (int m = 0; m < TM; m++)
            #pragma unroll
            for (int n = 0; n < TN; n++)
                acc[m][n] = bias ? bias[cj + n] : 0.f;
        #pragma unroll 2
        for (int i0 = 0; i0 < NIN; i0 += 4) {
            float xr[TM][4];
            #pragma unroll
            for (int m = 0; m < TM; m++) {
                float4 x4 = *reinterpret_cast<const float4*>(xb + m * NIN + i0);
                xr[m][0] = x4.x; xr[m][1] = x4.y; xr[m][2] = x4.z; xr[m][3] = x4.w;
            }
            #pragma unroll
            for (int ii = 0; ii < 4; ii++) {
                float w[TN];
                if (TN == 4) {
                    float4 w4 = *reinterpret_cast<const float4*>(W + (i0 + ii) * NOUT + cj);
                    w[0] = w4.x; w[1] = w4.y; w[2] = w4.z; w[3] = w4.w;
                } else if (TN == 2) {
                    float2 w2 = *reinterpret_cast<const float2*>(W + (i0 + ii) * NOUT + cj);
                    w[0] = w2.x; w[1] = w2.y;
                } else {
                    #pragma unroll
                    for (int n = 0; n < TN; n++) w[n] = W[(i0 + ii) * NOUT + cj + n];
                }
                #pragma unroll
                for (int m = 0; m < TM; m++)
                    #pragma unroll
                    for (int n = 0; n < TN; n++)
                        acc[m][n] = fmaf(xr[m][ii], w[n], acc[m][n]);
            }
        }
        #pragma unroll
        for (int m = 0; m < TM; m++)
            #pragma unroll
            for (int n = 0; n < TN; n++) {
                float r = acc[m][n];
                if (ACT == 1) r = r / (1.f + expf(-r));
                yb[m * NOUT + n] = r;
            }
    }
}

// ---------------- K0: init accumulators ------------------------------------
__global__ void init_kernel() {
    int i = blockIdx.x * blockDim.x + threadIdx.x;
    int stride = gridDim.x * blockDim.x;
    if (i < NN*4) { g_menc[i] = 0u; g_den[i] = 0.f; }
    for (int k = i; k < NN*SD; k += stride) g_outs[k] = 0.f;
    for (int k = i; k < NN*V3; k += stride) g_outv[k] = 0.f;
}

// ---------------- K1: node pre-linears --------------------------------------
__global__ __launch_bounds__(128) void node_pre(
    const float* __restrict__ ni,
    const float* __restrict__ Wss, const float* __restrict__ bss,
    const float* __restrict__ Wsv,
    const float* __restrict__ Wds, const float* __restrict__ Wdv)
{
    int n = blockIdx.x, tid = threadIdx.x;
    __shared__ float s[128], v[192];
    s[tid] = ni[n*320 + tid];
    for (int k = tid; k < 192; k += 128) v[k] = ni[n*320 + 128 + k];
    __syncthreads();
    float a1 = bss[tid], a2 = 0.f;
    #pragma unroll 4
    for (int i = 0; i < 128; i++) {
        float si = s[i];
        a1 = fmaf(si, Wss[i*128 + tid], a1);
        a2 = fmaf(si, Wds[i*128 + tid], a2);
    }
    g_ms[n*128 + tid] = a1;
    g_ds[n*128 + tid] = a2;
    for (int o = tid; o < 192; o += 128) {
        int i = o >> 6, d = o & 63;
        float m1 = 0.f, m2 = 0.f;
        #pragma unroll 4
        for (int c = 0; c < 64; c++) {
            float x = v[c*3 + i];
            m1 = fmaf(x, Wsv[c*64 + d], m1);
            m2 = fmaf(x, Wdv[c*64 + d], m2);
        }
        g_mv[n*192 + d*3 + i] = m1;
        g_dv[n*192 + d*3 + i] = m2;
    }
}

// ---------------- K2: fused per-edge megakernel -----------------------------
// smem pool layout (floats), phase-overlaid:
#define P_ES   0        /* [8][128]  also sc (late) */
#define P_EV   1024     /* [8][192]  also gs (late) */
#define P_WB   2560     /* [8][448]  also gv [24][64] @2560, vls [8][128] @4096 */
#define P_GV   2560
#define P_VLS  4096
#define P_STP  6144     /* [8][192]  also s2 */
#define P_VTP  7680     /* [24][256] also v2  ([e][i][c]) */
#define P_VLV  13824    /* [24][64]  ([e][i][d]) */
#define P_WF   15360    /* [8][160] */
#define P_H0   16640    /* [8][64] */
#define P_H1   17152    /* [8][64] */
#define P_W2S  17664    /* [448] */
#define P_YV   18112    /* [8][4] */
#define SMEM_FLOATS 18144

__global__ __launch_bounds__(THREADS) void edge_kernel(
    const int*   __restrict__ esrc, const int* __restrict__ edst,
    const float* __restrict__ eattr, const float* __restrict__ eemb,
    const float* __restrict__ nattr,
    const float* __restrict__ rW0, const float* __restrict__ rb0,
    const float* __restrict__ rW1, const float* __restrict__ rb1,
    const float* __restrict__ rW2, const float* __restrict__ rb2,
    const float* __restrict__ attWs, const float* __restrict__ attbs,
    const float* __restrict__ l1Ws, const float* __restrict__ l1bs,
    const float* __restrict__ l1Wv, const float* __restrict__ tp2w,
    const float* __restrict__ l2Ws, const float* __restrict__ l2bs,
    const float* __restrict__ l2Wv, const float* __restrict__ attdot)
{
    extern __shared__ float sm[];
    __shared__ int ssrc[EB], sdst[EB];
    const int tid = threadIdx.x;
    const int e0  = blockIdx.x * EB;

    float* es  = sm + P_ES;
    float* ev  = sm + P_EV;
    float* wb  = sm + P_WB;
    float* sc  = sm + P_ES;
    float* gs  = sm + P_EV;
    float* gv  = sm + P_GV;
    float* vls = sm + P_VLS;
    float* stp = sm + P_STP;
    float* vtp = sm + P_VTP;
    float* vlv = sm + P_VLV;
    float* wf  = sm + P_WF;
    float* h0  = sm + P_H0;
    float* h1  = sm + P_H1;
    float* w2s = sm + P_W2S;
    float* yv  = sm + P_YV;

    if (tid < EB)   { ssrc[tid] = esrc[e0 + tid]; sdst[tid] = edst[e0 + tid]; }
    if (tid < EB*4) yv[tid] = eattr[e0*4 + tid];
    for (int t = tid; t < NWW; t += THREADS) w2s[t] = tp2w[t];
    __syncthreads();

    // A: gather es, ev; assemble wf (float4 paths)
    for (int t = tid; t < EB*32; t += THREADS) {
        int e = t >> 5, q = t & 31;
        float4 a = *reinterpret_cast<const float4*>(g_ms + ssrc[e]*SD + q*4);
        float4 b = *reinterpret_cast<const float4*>(g_ds + sdst[e]*SD + q*4);
        float4 r = make_float4(a.x+b.x, a.y+b.y, a.z+b.z, a.w+b.w);
        *reinterpret_cast<float4*>(es + t*4) = r;
    }
    for (int t = tid; t < EB*48; t += THREADS) {
        int e = t / 48, q = t - e*48;
        float4 a = *reinterpret_cast<const float4*>(g_mv + ssrc[e]*V3 + q*4);
        float4 b = *reinterpret_cast<const float4*>(g_dv + sdst[e]*V3 + q*4);
        float4 r = make_float4(a.x+b.x, a.y+b.y, a.z+b.z, a.w+b.w);
        *reinterpret_cast<float4*>(ev + t*4) = r;
    }
    for (int t = tid; t < EB*40; t += THREADS) {
        int e = t / 40, q = t - e*40;
        float4 val;
        if (q < 8)       val = *reinterpret_cast<const float4*>(eemb + (e0+e)*32 + q*4);
        else if (q < 24) val = *reinterpret_cast<const float4*>(nattr + ssrc[e]*64 + (q-8)*4);
        else             val = *reinterpret_cast<const float4*>(nattr + sdst[e]*64 + (q-24)*4);
        *reinterpret_cast<float4*>(wf + e*160 + q*4) = val;
    }
    __syncthreads();

    // B: radial MLP 160 -> 64 -> 64 -> 448
    gemm_rt<160, 64, EB, 2, 2, 1>(rW0, rb0, wf, h0);
    __syncthreads();
    gemm_rt< 64, 64, EB, 2, 2, 1>(rW1, rb1, h0, h1);
    __syncthreads();
    gemm_rt< 64,448, EB, 4, 4, 0>(rW2, rb2, h1, wb);
    __syncthreads();

    // C: DTP1 -> stp [8][192], vtp [24][256] ([e][i][c])
    for (int t = tid; t < EB*192; t += THREADS) {
        int e = t / 192, c = t - e*192;
        const float* y = yv + e*4;
        if (c < 128) {
            stp[t] = wb[e*448 + c] * es[e*128 + c] * y[0];
        } else {
            int cc = c - 128;
            const float* vv = ev + e*192 + cc*3;
            stp[t] = wb[e*448 + 320 + cc] * (vv[0]*y[1] + vv[1]*y[2] + vv[2]*y[3]);
        }
    }
    for (int t = tid; t < EB*256; t += THREADS) {
        int e = t >> 8, c = t & 255;
        const float* y = yv + e*4;
        float ox, oy, oz;
        if (c < 128) {
            float a = wb[e*448 + 128 + c] * es[e*128 + c];
            ox = a*y[1]; oy = a*y[2]; oz = a*y[3];
        } else if (c < 192) {
            int cc = c - 128;
            float a = wb[e*448 + 256 + cc] * y[0];
            const float* vv = ev + e*192 + cc*3;
            ox = a*vv[0]; oy = a*vv[1]; oz = a*vv[2];
        } else {
            int cc = c - 192;
            float wc = wb[e*448 + 384 + cc];
            const float* vv = ev + e*192 + cc*3;
            ox = wc*(vv[1]*y[3] - vv[2]*y[2]);
            oy = wc*(vv[2]*y[1] - vv[0]*y[3]);
            oz = wc*(vv[0]*y[2] - vv[1]*y[1]);
        }
        vtp[e*768 +       c] = ox;
        vtp[e*768 + 256 + c] = oy;
        vtp[e*768 + 512 + c] = oz;
    }
    __syncthreads();

    // D: sc / gs / gv  (read stp/vtp; write regions dead since DTP1)
    gemm_rt<192, 128, EB,   2, 2, 0>(attWs, attbs, stp, sc);
    gemm_rt<192, 192, EB,   2, 4, 0>(l1Ws,  l1bs,  stp, gs);
    gemm_rt<256,  64, EB*3, 3, 2, 0>(l1Wv,  (const float*)nullptr, vtp, gv);
    __syncthreads();

    // E: gates in place
    for (int t = tid; t < EB*128; t += THREADS) {
        int e = t >> 7, c = t & 127;
        float x = gs[e*192 + c];
        gs[e*192 + c] = x / (1.f + expf(-x));
    }
    for (int t = tid; t < EB*64; t += THREADS) {
        int e = t >> 6, c = t & 63;
        float sg = 1.f / (1.f + expf(-gs[e*192 + 128 + c]));
        gv[e*192 +       c] *= sg;
        gv[e*192 +  64 + c] *= sg;
        gv[e*192 + 128 + c] *= sg;
    }
    __syncthreads();

    // F: DTP2 -> s2 (stp), v2 (vtp)
    for (int t = tid; t < EB*192; t += THREADS) {
        int e = t / 192, c = t - e*192;
        const float* y = yv + e*4;
        if (c < 128) {
            stp[t] = w2s[c] * gs[e*192 + c] * y[0];
        } else {
            int cc = c - 128;
            float vx = gv[e*192 + cc], vy = gv[e*192 + 64 + cc], vz = gv[e*192 + 128 + cc];
            stp[t] = w2s[320 + cc] * (vx*y[1] + vy*y[2] + vz*y[3]);
        }
    }
    __syncthreads();  // stp reuse ordering vs D reads already done; vtp written next reads gv
    for (int t = tid; t < EB*256; t += THREADS) {
        int e = t >> 8, c = t & 255;
        const float* y = yv + e*4;
        float ox, oy, oz;
        if (c < 128) {
            float a = w2s[128 + c] * gs[e*192 + c];
            ox = a*y[1]; oy = a*y[2]; oz = a*y[3];
        } else if (c < 192) {
            int cc = c - 128;
            float a = w2s[256 + cc] * y[0];
            ox = a*gv[e*192 + cc]; oy = a*gv[e*192 + 64 + cc]; oz = a*gv[e*192 + 128 + cc];
        } else {
            int cc = c - 192;
            float wc = w2s[384 + cc];
            float vx = gv[e*192 + cc], vy = gv[e*192 + 64 + cc], vz = gv[e*192 + 128 + cc];
            ox = wc*(vy*y[3] - vz*y[2]);
            oy = wc*(vz*y[1] - vx*y[3]);
            oz = wc*(vx*y[2] - vy*y[1]);
        }
        vtp[e*768 +       c] = ox;
        vtp[e*768 + 256 + c] = oy;
        vtp[e*768 + 512 + c] = oz;
    }
    __syncthreads();

    // G: val_s / val_v
    gemm_rt<192, 128, EB,   2, 2, 0>(l2Ws, l2bs, stp, vls);
    gemm_rt<256,  64, EB*3, 3, 2, 0>(l2Wv, (const float*)nullptr, vtp, vlv);
    __syncthreads();

    // H: logits + stores
    if (tid < EB*4) {
        int e = tid >> 2, h = tid & 3;
        float acc = 0.f;
        #pragma unroll 8
        for (int k = 0; k < 32; k++) {
            float x = sc[e*128 + h*32 + k];
            float sg = 1.f / (1.f + expf(-x));
            float sl = 0.6f*x + 0.4f*x*(2.f*sg - 1.f);
            acc = fmaf(sl, attdot[h*32 + k], acc);
        }
        g_logit[(e0+e)*4 + h] = acc;
        atomicMax(&g_menc[sdst[e]*4 + h], f2ord(acc));
    }
    for (int t = tid; t < EB*32; t += THREADS)
        *reinterpret_cast<float4*>(g_vals + e0*SD + t*4) =
            *reinterpret_cast<const float4*>(vls + t*4);
    for (int t = tid; t < EB*48; t += THREADS)
        *reinterpret_cast<float4*>(g_valv + e0*V3 + t*4) =
            *reinterpret_cast<const float4*>(vlv + t*4);
}

// ---------------- K3: z = exp(logit - m), accumulate den --------------------
__global__ void softmax_z(const int* __restrict__ edst) {
    int i = blockIdx.x * blockDim.x + threadIdx.x;
    if (i >= NE*4) return;
    int e = i >> 2, h = i & 3;
    int d = edst[e];
    float m = ord2f(g_menc[d*4 + h]);
    float z = expf(g_logit[i] - m);
    g_zz[i] = z;
    atomicAdd(&g_den[d*4 + h], z);
}

// ---------------- K4: alpha-weighted scatter --------------------------------
__global__ __launch_bounds__(192) void scatter_kernel(const int* __restrict__ edst) {
    int e = blockIdx.x;
    int tid = threadIdx.x;
    __shared__ float a[4];
    int d = edst[e];
    if (tid < 4) a[tid] = g_zz[e*4 + tid] / (g_den[d*4 + tid] + 1e-12f);
    __syncthreads();
    if (tid < 128)
        atomicAdd(&g_outs[d*128 + tid], g_vals[e*128 + tid] * a[tid >> 5]);
    // g_valv layout [e][i*64+d]: head = (channel)>>4 where channel = t & 63
    atomicAdd(&g_outv[d*192 + tid], g_valv[e*192 + tid] * a[(tid & 63) >> 4]);
}

// ---------------- K5: final node linears -> d_out ---------------------------
__global__ __launch_bounds__(128) void node_post(
    const float* __restrict__ oWs, const float* __restrict__ obs,
    const float* __restrict__ oWv, float* __restrict__ out)
{
    int n = blockIdx.x, tid = threadIdx.x;
    __shared__ float os[128], ov[192];  // ov layout [i*64+c]
    os[tid] = g_outs[n*128 + tid];
    for (int k = tid; k < 192; k += 128) ov[k] = g_outv[n*192 + k];
    __syncthreads();
    float acc = obs[tid];
    #pragma unroll 4
    for (int i = 0; i < 128; i++)
        acc = fmaf(os[i], oWs[i*128 + tid], acc);
    out[n*320 + tid] = acc;
    for (int o = tid; o < 192; o += 128) {
        int i = o >> 6, d = o & 63;
        float a2 = 0.f;
        #pragma unroll 4
        for (int c = 0; c < 64; c++)
            a2 = fmaf(ov[i*64 + c], oWv[c*64 + d], a2);
        out[n*320 + 128 + d*3 + i] = a2;
    }
}

// ---------------- host launcher ---------------------------------------------
extern "C" void kernel_launch(void* const* d_in, const int* in_sizes, int n_in,
                              void* d_out, int out_size)
{
    const float* node_input = (const float*)d_in[0];
    const float* node_attr  = (const float*)d_in[1];
    const int *esrc, *edst;
    const float *eattr, *eemb;
    if (in_sizes[2] == NE) {           // reference-signature order
        esrc  = (const int*)d_in[2];
        edst  = (const int*)d_in[3];
        eattr = (const float*)d_in[4];
        eemb  = (const float*)d_in[5];
    } else {                            // setup_inputs dict order
        eattr = (const float*)d_in[2];
        eemb  = (const float*)d_in[3];
        esrc  = (const int*)d_in[4];
        edst  = (const int*)d_in[5];
    }
    const float* Wss   = (const float*)d_in[6];
    const float* bss   = (const float*)d_in[7];
    const float* Wsv   = (const float*)d_in[8];
    const float* Wds   = (const float*)d_in[9];
    const float* Wdv   = (const float*)d_in[10];
    const float* rW0   = (const float*)d_in[11];
    const float* rb0   = (const float*)d_in[12];
    const float* rW1   = (const float*)d_in[13];
    const float* rb1   = (const float*)d_in[14];
    const float* rW2   = (const float*)d_in[15];
    const float* rb2   = (const float*)d_in[16];
    const float* l1Ws  = (const float*)d_in[17];
    const float* l1bs  = (const float*)d_in[18];
    const float* l1Wv  = (const float*)d_in[19];
    const float* attWs = (const float*)d_in[20];
    const float* attbs = (const float*)d_in[21];
    const float* tp2w  = (const float*)d_in[22];
    const float* l2Ws  = (const float*)d_in[23];
    const float* l2bs  = (const float*)d_in[24];
    const float* l2Wv  = (const float*)d_in[25];
    const float* attdot= (const float*)d_in[26];
    const float* oWs   = (const float*)d_in[27];
    const float* obs   = (const float*)d_in[28];
    const float* oWv   = (const float*)d_in[29];

    static bool attr_set = false;
    if (!attr_set) {
        cudaFuncSetAttribute(edge_kernel,
                             cudaFuncAttributeMaxDynamicSharedMemorySize,
                             SMEM_FLOATS * 4);
        attr_set = true;
    }

    init_kernel<<<(NN*V3 + 255)/256, 256>>>();
    node_pre<<<NN, 128>>>(node_input, Wss, bss, Wsv, Wds, Wdv);
    edge_kernel<<<NE/EB, THREADS, SMEM_FLOATS*4>>>(esrc, edst, eattr, eemb, node_attr,
                                      rW0, rb0, rW1, rb1, rW2, rb2,
                                      attWs, attbs, l1Ws, l1bs, l1Wv,
                                      tp2w, l2Ws, l2bs, l2Wv, attdot);
    softmax_z<<<(NE*4 + 255)/256, 256>>>(edst);
    scatter_kernel<<<NE, 192>>>(edst);
    node_post<<<NN, 128>>>(oWs, obs, oWv, (float*)d_out);
}